// round 5
// baseline (speedup 1.0000x reference)
#include <cuda_runtime.h>
#include <cuda_bf16.h>
#include <math.h>
#include <stdint.h>

// ---------------- constants ----------------
#define N_NODES  100000
#define N_EDGES  1600000
#define FEAT     128
#define N_GRAPHS 64
#define N_CLASSES 10

#define SCAN_BLK   1024
#define SCAN_NBLK  ((N_NODES + SCAN_BLK - 1) / SCAN_BLK)   // 98

// ---------------- device scratch ----------------
__device__ float g_S1[(size_t)N_NODES * FEAT];
__device__ float g_S2[(size_t)N_NODES * FEAT];
__device__ float g_S3[(size_t)N_NODES * FEAT];

__device__ int   g_src[N_EDGES];
__device__ int   g_dst[N_EDGES];
__device__ int   g_csr[N_EDGES];
__device__ int   g_batch[N_NODES];
__device__ int   g_indeg[N_NODES];
__device__ int   g_rowstart[N_NODES + 1];
__device__ int   g_pos[N_NODES];
__device__ float g_dinv[N_NODES];
__device__ float g_rcnt[N_NODES];
__device__ float g_pool[N_GRAPHS * FEAT];
__device__ int   g_gcnt[N_GRAPHS];
__device__ int   g_blocksum[SCAN_NBLK];
__device__ int   g_blockoff[SCAN_NBLK];
__device__ int   g_is64;

// ---------------- index dtype detection ----------------
__global__ void detect_kernel(const void* ei) {
    const unsigned long long* p = (const unsigned long long*)ei;
    unsigned long long v = p[threadIdx.x];
    unsigned int hi = (unsigned int)(v >> 32);
    unsigned int any = __ballot_sync(0xffffffffu, hi != 0u);
    __shared__ int s_any;
    if (threadIdx.x == 0) s_any = 0;
    __syncthreads();
    if (any != 0u && (threadIdx.x & 31) == 0) atomicOr(&s_any, 1);
    __syncthreads();
    if (threadIdx.x == 0) g_is64 = s_any ? 0 : 1;
}

__global__ void zero_kernel() {
    int i = blockIdx.x * blockDim.x + threadIdx.x;
    if (i < N_NODES) g_indeg[i] = 0;
    if (i < N_GRAPHS * FEAT) g_pool[i] = 0.0f;
}

__global__ void convert_hist_kernel(const void* ei, const void* bt) {
    int i = blockIdx.x * blockDim.x + threadIdx.x;
    const int is64 = g_is64;
    if (i < N_EDGES) {
        int s, d;
        if (is64) {
            s = (int)((const long long*)ei)[i];
            d = (int)((const long long*)ei)[(size_t)N_EDGES + i];
        } else {
            s = ((const int*)ei)[i];
            d = ((const int*)ei)[N_EDGES + i];
        }
        g_src[i] = s;
        g_dst[i] = d;
        atomicAdd(&g_indeg[d], 1);
    }
    if (i < N_NODES) {
        g_batch[i] = is64 ? (int)((const long long*)bt)[i] : ((const int*)bt)[i];
    }
}

// ---------------- 3-phase multi-block scan ----------------
__global__ __launch_bounds__(SCAN_BLK) void scan1_kernel() {
    __shared__ int warp_s[32];
    int idx = blockIdx.x * SCAN_BLK + threadIdx.x;
    int v = (idx < N_NODES) ? g_indeg[idx] : 0;
#pragma unroll
    for (int o = 16; o > 0; o >>= 1) v += __shfl_down_sync(0xffffffffu, v, o);
    int wid = threadIdx.x >> 5, lane = threadIdx.x & 31;
    if (lane == 0) warp_s[wid] = v;
    __syncthreads();
    if (wid == 0) {
        int s = (lane < SCAN_BLK / 32) ? warp_s[lane] : 0;
#pragma unroll
        for (int o = 16; o > 0; o >>= 1) s += __shfl_down_sync(0xffffffffu, s, o);
        if (lane == 0) g_blocksum[blockIdx.x] = s;
    }
}

__global__ void scan2_kernel() {
    __shared__ int sm[SCAN_NBLK];
    int t = threadIdx.x;
    int v = (t < SCAN_NBLK) ? g_blocksum[t] : 0;
    if (t < SCAN_NBLK) sm[t] = v;
    __syncthreads();
    if (t == 0) {
        int run = 0;
        for (int i = 0; i < SCAN_NBLK; i++) { int c = sm[i]; sm[i] = run; run += c; }
        g_rowstart[N_NODES] = run;
    }
    __syncthreads();
    if (t < SCAN_NBLK) g_blockoff[t] = sm[t];
}

__global__ __launch_bounds__(SCAN_BLK) void scan3_kernel() {
    __shared__ int warp_s[32];
    int idx = blockIdx.x * SCAN_BLK + threadIdx.x;
    int wid = threadIdx.x >> 5, lane = threadIdx.x & 31;
    int c = (idx < N_NODES) ? g_indeg[idx] : 0;
    int v = c;
#pragma unroll
    for (int o = 1; o < 32; o <<= 1) {
        int u = __shfl_up_sync(0xffffffffu, v, o);
        if (lane >= o) v += u;
    }
    if (lane == 31) warp_s[wid] = v;
    __syncthreads();
    if (wid == 0) {
        int s = (lane < SCAN_BLK / 32) ? warp_s[lane] : 0;
#pragma unroll
        for (int o = 1; o < 32; o <<= 1) {
            int u = __shfl_up_sync(0xffffffffu, s, o);
            if (lane >= o) s += u;
        }
        if (lane < SCAN_BLK / 32) warp_s[lane] = s;
    }
    __syncthreads();
    int excl = v - c + (wid > 0 ? warp_s[wid - 1] : 0) + g_blockoff[blockIdx.x];
    if (idx < N_NODES) {
        g_rowstart[idx] = excl;
        g_pos[idx]      = excl;
        g_dinv[idx]     = rsqrtf((float)c + 1.0f);
        g_rcnt[idx]     = 1.0f / (float)max(c, 1);
    }
}

__global__ void scatter_kernel() {
    int e = blockIdx.x * blockDim.x + threadIdx.x;
    if (e < N_EDGES) {
        int d = g_dst[e];
        int p = atomicAdd(&g_pos[d], 1);
        g_csr[p] = g_src[e];
    }
}

// ---------------- bf16 split-precision tensor-core GEMM ----------------
// out[M,128] = A@W^T (+bias) (+= out if acc)
__device__ __forceinline__ void mma_bf16(float* c, const uint32_t* a, const uint32_t* b) {
    asm volatile(
        "mma.sync.aligned.m16n8k16.row.col.f32.bf16.bf16.f32 "
        "{%0,%1,%2,%3}, {%4,%5,%6,%7}, {%8,%9}, {%0,%1,%2,%3};\n"
        : "+f"(c[0]), "+f"(c[1]), "+f"(c[2]), "+f"(c[3])
        : "r"(a[0]), "r"(a[1]), "r"(a[2]), "r"(a[3]), "r"(b[0]), "r"(b[1]));
}

__device__ __forceinline__ void split2(float x, float y, uint32_t& hi, uint32_t& lo) {
    __nv_bfloat162 h = __floats2bfloat162_rn(x, y);
    float2 hf = __bfloat1622float2(h);
    __nv_bfloat162 l = __floats2bfloat162_rn(x - hf.x, y - hf.y);
    hi = *reinterpret_cast<uint32_t*>(&h);
    lo = *reinterpret_cast<uint32_t*>(&l);
}

#define SMW 20

__global__ __launch_bounds__(256, 2) void gemm_one(
    const float* __restrict__ A, const float* __restrict__ W,
    const float* __restrict__ bias, float* __restrict__ out,
    int M, int accFlag)
{
    __shared__ uint32_t sAhi[128][SMW], sAlo[128][SMW];
    __shared__ uint32_t sWhi[128][SMW], sWlo[128][SMW];

    const int t    = threadIdx.x;
    const int warp = t >> 5;
    const int lane = t & 31;
    const int wm   = warp >> 1;
    const int wn   = warp & 1;
    const int m0   = blockIdx.x * 128;
    const int r    = lane >> 2;
    const int kq   = lane & 3;

    float acc[2][8][4];
#pragma unroll
    for (int i = 0; i < 2; i++)
#pragma unroll
        for (int j = 0; j < 8; j++)
#pragma unroll
            for (int q = 0; q < 4; q++) acc[i][j][q] = 0.0f;

    for (int k0 = 0; k0 < 128; k0 += 32) {
#pragma unroll
        for (int i = 0; i < 4; i++) {
            int slot = t + i * 256;
            int row  = slot >> 3;
            int c4   = slot & 7;
            int ar   = m0 + row; if (ar >= M) ar = M - 1;
            float4 av = __ldg((const float4*)(A + (size_t)ar * 128 + k0 + c4 * 4));
            uint32_t h0, l0, h1, l1;
            split2(av.x, av.y, h0, l0);
            split2(av.z, av.w, h1, l1);
            sAhi[row][c4 * 2] = h0;  sAhi[row][c4 * 2 + 1] = h1;
            sAlo[row][c4 * 2] = l0;  sAlo[row][c4 * 2 + 1] = l1;
            float4 wv = __ldg((const float4*)(W + (size_t)row * 128 + k0 + c4 * 4));
            split2(wv.x, wv.y, h0, l0);
            split2(wv.z, wv.w, h1, l1);
            sWhi[row][c4 * 2] = h0;  sWhi[row][c4 * 2 + 1] = h1;
            sWlo[row][c4 * 2] = l0;  sWlo[row][c4 * 2 + 1] = l1;
        }
        __syncthreads();

#pragma unroll
        for (int kk = 0; kk < 32; kk += 16) {
            const int kw = kk >> 1;
            uint32_t ah[2][4], al[2][4];
#pragma unroll
            for (int mt = 0; mt < 2; mt++) {
                int mr = wm * 32 + mt * 16;
                ah[mt][0] = sAhi[mr + r][kw + kq];
                ah[mt][1] = sAhi[mr + r + 8][kw + kq];
                ah[mt][2] = sAhi[mr + r][kw + kq + 4];
                ah[mt][3] = sAhi[mr + r + 8][kw + kq + 4];
                al[mt][0] = sAlo[mr + r][kw + kq];
                al[mt][1] = sAlo[mr + r + 8][kw + kq];
                al[mt][2] = sAlo[mr + r][kw + kq + 4];
                al[mt][3] = sAlo[mr + r + 8][kw + kq + 4];
            }
#pragma unroll
            for (int g = 0; g < 2; g++) {
                uint32_t bh[4][2], bl[4][2];
#pragma unroll
                for (int n2 = 0; n2 < 4; n2++) {
                    int nr = wn * 64 + g * 32 + n2 * 8 + r;
                    bh[n2][0] = sWhi[nr][kw + kq];
                    bh[n2][1] = sWhi[nr][kw + kq + 4];
                    bl[n2][0] = sWlo[nr][kw + kq];
                    bl[n2][1] = sWlo[nr][kw + kq + 4];
                }
#pragma unroll
                for (int mt = 0; mt < 2; mt++)
#pragma unroll
                    for (int n2 = 0; n2 < 4; n2++) {
                        float* c = acc[mt][g * 4 + n2];
                        mma_bf16(c, ah[mt], bh[n2]);
                        mma_bf16(c, ah[mt], bl[n2]);
                        mma_bf16(c, al[mt], bh[n2]);
                    }
            }
        }
        __syncthreads();
    }

#pragma unroll
    for (int mt = 0; mt < 2; mt++) {
#pragma unroll
        for (int nt = 0; nt < 8; nt++) {
            int gcol = wn * 64 + nt * 8 + kq * 2;
            float b0 = 0.f, b1 = 0.f;
            if (bias) { b0 = bias[gcol]; b1 = bias[gcol + 1]; }
            int grow = m0 + wm * 32 + mt * 16 + r;
            if (grow < M) {
                float* p = out + (size_t)grow * 128 + gcol;
                float v0 = acc[mt][nt][0] + b0;
                float v1 = acc[mt][nt][1] + b1;
                if (accFlag) { v0 += p[0]; v1 += p[1]; }
                p[0] = v0; p[1] = v1;
            }
            int grow2 = grow + 8;
            if (grow2 < M) {
                float* p = out + (size_t)grow2 * 128 + gcol;
                float v0 = acc[mt][nt][2] + b0;
                float v1 = acc[mt][nt][3] + b1;
                if (accFlag) { v0 += p[0]; v1 += p[1]; }
                p[0] = v0; p[1] = v1;
            }
        }
    }
}

// ---------------- CSR gathers ----------------
__global__ __launch_bounds__(256) void gcn_gather_kernel(
    const float* __restrict__ xw, float* __restrict__ out,
    const float* __restrict__ bias)
{
    int w = (blockIdx.x * blockDim.x + threadIdx.x) >> 5;
    int lane = threadIdx.x & 31;
    if (w >= N_NODES) return;
    int beg = g_rowstart[w], end = g_rowstart[w + 1];
    float dn = g_dinv[w];
    float4 acc = make_float4(0.f, 0.f, 0.f, 0.f);
    for (int b = beg; b < end; b += 32) {
        int nb = min(32, end - b);
        int s_l = 0; float d_l = 0.f;
        if (b + lane < end) { s_l = g_csr[b + lane]; d_l = g_dinv[s_l]; }
        for (int j = 0; j < nb; j++) {
            int   s  = __shfl_sync(0xffffffffu, s_l, j);
            float nm = __shfl_sync(0xffffffffu, d_l, j) * dn;
            float4 v = __ldg((const float4*)(xw + (size_t)s * 128 + lane * 4));
            acc.x += v.x * nm; acc.y += v.y * nm;
            acc.z += v.z * nm; acc.w += v.w * nm;
        }
    }
    float4 sv = *(const float4*)(xw + (size_t)w * 128 + lane * 4);
    float d2 = dn * dn;
    float4 bv = *(const float4*)(bias + lane * 4);
    acc.x += sv.x * d2 + bv.x; acc.y += sv.y * d2 + bv.y;
    acc.z += sv.z * d2 + bv.z; acc.w += sv.w * d2 + bv.w;
    *(float4*)(out + (size_t)w * 128 + lane * 4) = acc;
}

__global__ __launch_bounds__(256) void sage_gather_kernel(
    const float* __restrict__ h, float* __restrict__ out)
{
    int w = (blockIdx.x * blockDim.x + threadIdx.x) >> 5;
    int lane = threadIdx.x & 31;
    if (w >= N_NODES) return;
    int beg = g_rowstart[w], end = g_rowstart[w + 1];
    float4 acc = make_float4(0.f, 0.f, 0.f, 0.f);
    for (int b = beg; b < end; b += 32) {
        int nb = min(32, end - b);
        int s_l = 0;
        if (b + lane < end) s_l = g_csr[b + lane];
        for (int j = 0; j < nb; j++) {
            int s = __shfl_sync(0xffffffffu, s_l, j);
            float4 v = __ldg((const float4*)(h + (size_t)s * 128 + lane * 4));
            acc.x += v.x; acc.y += v.y; acc.z += v.z; acc.w += v.w;
        }
    }
    float rc = g_rcnt[w];
    acc.x *= rc; acc.y *= rc; acc.z *= rc; acc.w *= rc;
    *(float4*)(out + (size_t)w * 128 + lane * 4) = acc;
}

// ---------------- pooling ----------------
__device__ __forceinline__ int lower_bound_batch(int val) {
    int lo = 0, hi = N_NODES;
    while (lo < hi) {
        int mid = (lo + hi) >> 1;
        if (g_batch[mid] < val) lo = mid + 1; else hi = mid;
    }
    return lo;
}

__global__ void pool_kernel(const float* __restrict__ h) {
    int g = blockIdx.x;
    int part = blockIdx.y;
    int f = threadIdx.x;
    int lo = lower_bound_batch(g);
    int hi = lower_bound_batch(g + 1);
    float acc = 0.f;
    for (int n = lo + part; n < hi; n += 8) acc += h[(size_t)n * 128 + f];
    atomicAdd(&g_pool[g * 128 + f], acc);
    if (part == 0 && f == 0) g_gcnt[g] = max(hi - lo, 1);
}

// ---------------- classifier MLP + softmax ----------------
__global__ void mlp_kernel(
    const float* __restrict__ w0, const float* __restrict__ b0,
    const float* __restrict__ w1, const float* __restrict__ b1,
    const float* __restrict__ w2, const float* __restrict__ b2,
    const float* __restrict__ w3, const float* __restrict__ b3,
    const float* __restrict__ bn0g, const float* __restrict__ bn0b,
    const float* __restrict__ bn1g, const float* __restrict__ bn1b,
    const float* __restrict__ bn2g, const float* __restrict__ bn2b,
    float* __restrict__ out)
{
    __shared__ float sin_[128], h0[200], h1[100], h2[50], lg[10];
    int g = blockIdx.x, t = threadIdx.x;
    if (t < 128) sin_[t] = g_pool[g * 128 + t] / (float)g_gcnt[g];
    __syncthreads();
    const float bnc = rsqrtf(1.0f + 1e-5f);
    if (t < 200) {
        float s = b0[t];
        const float* wr = w0 + (size_t)t * 128;
#pragma unroll 4
        for (int k = 0; k < 128; k++) s += wr[k] * sin_[k];
        h0[t] = tanhf(s * bn0g[t] * bnc + bn0b[t]);
    }
    __syncthreads();
    if (t < 100) {
        float s = b1[t];
        const float* wr = w1 + (size_t)t * 200;
#pragma unroll 4
        for (int k = 0; k < 200; k++) s += wr[k] * h0[k];
        h1[t] = tanhf(s * bn1g[t] * bnc + bn1b[t]);
    }
    __syncthreads();
    if (t < 50) {
        float s = b2[t];
        const float* wr = w2 + (size_t)t * 100;
#pragma unroll 4
        for (int k = 0; k < 100; k++) s += wr[k] * h1[k];
        h2[t] = tanhf(s * bn2g[t] * bnc + bn2b[t]);
    }
    __syncthreads();
    if (t < 10) {
        float s = b3[t];
        const float* wr = w3 + (size_t)t * 50;
#pragma unroll
        for (int k = 0; k < 50; k++) s += wr[k] * h2[k];
        lg[t] = s;
    }
    __syncthreads();
    if (t == 0) {
        float m = lg[0];
        for (int c = 1; c < N_CLASSES; c++) m = fmaxf(m, lg[c]);
        float e[N_CLASSES];
        float sum = 0.f;
        for (int c = 0; c < N_CLASSES; c++) { e[c] = expf(lg[c] - m); sum += e[c]; }
        float inv = 1.0f / sum;
        for (int c = 0; c < N_CLASSES; c++) out[g * N_CLASSES + c] = e[c] * inv;
    }
}

// ---------------- launch ----------------
extern "C" void kernel_launch(void* const* d_in, const int* in_sizes, int n_in,
                              void* d_out, int out_size)
{
    const float* x       = (const float*)d_in[0];
    const void*  ei      = d_in[1];
    const void*  bt      = d_in[2];
    const float* gcn_w   = (const float*)d_in[3];
    const float* gcn_b   = (const float*)d_in[4];
    const float* s1_wl   = (const float*)d_in[5];
    const float* s1_bl   = (const float*)d_in[6];
    const float* s1_wr   = (const float*)d_in[7];
    const float* s2_wl   = (const float*)d_in[8];
    const float* s2_bl   = (const float*)d_in[9];
    const float* s2_wr   = (const float*)d_in[10];
    const float* c_w0 = (const float*)d_in[11]; const float* c_b0 = (const float*)d_in[12];
    const float* c_w1 = (const float*)d_in[13]; const float* c_b1 = (const float*)d_in[14];
    const float* c_w2 = (const float*)d_in[15]; const float* c_b2 = (const float*)d_in[16];
    const float* c_w3 = (const float*)d_in[17]; const float* c_b3 = (const float*)d_in[18];
    const float* bn0g = (const float*)d_in[19]; const float* bn0b = (const float*)d_in[20];
    const float* bn1g = (const float*)d_in[21]; const float* bn1b = (const float*)d_in[22];
    const float* bn2g = (const float*)d_in[23]; const float* bn2b = (const float*)d_in[24];
    float* out = (float*)d_out;

    float *S1, *S2, *S3;
    cudaGetSymbolAddress((void**)&S1, g_S1);
    cudaGetSymbolAddress((void**)&S2, g_S2);
    cudaGetSymbolAddress((void**)&S3, g_S3);

    // side stream + events for fork-join overlap inside graph capture.
    static cudaStream_t s_side = nullptr;
    static cudaEvent_t  s_ev[6] = {nullptr};
    if (s_side == nullptr) {
        cudaStreamCreateWithFlags(&s_side, cudaStreamNonBlocking);
        for (int i = 0; i < 6; i++)
            cudaEventCreateWithFlags(&s_ev[i], cudaEventDisableTiming);
    }

    const int TB = 256;
    const int nodeBlocks   = (N_NODES + TB - 1) / TB;
    const int edgeBlocks   = (N_EDGES + TB - 1) / TB;
    const int gatherBlocks = (N_NODES + 7) / 8;
    const int gemmBlocks   = (N_NODES + 127) / 128;

    // === fork 0: GCN GEMM (needs only x, gcn_w) overlaps CSR build ===
    detect_kernel<<<1, 256>>>(ei);
    cudaEventRecord(s_ev[0], 0);
    cudaStreamWaitEvent(s_side, s_ev[0], 0);
    gemm_one<<<gemmBlocks, 256, 0, s_side>>>(x, gcn_w, nullptr, S1, N_NODES, 0);

    // main: CSR build
    zero_kernel<<<nodeBlocks, TB>>>();
    convert_hist_kernel<<<edgeBlocks, TB>>>(ei, bt);
    scan1_kernel<<<SCAN_NBLK, SCAN_BLK>>>();
    scan2_kernel<<<1, 128>>>();
    scan3_kernel<<<SCAN_NBLK, SCAN_BLK>>>();
    scatter_kernel<<<edgeBlocks, TB>>>();

    // join 0
    cudaEventRecord(s_ev[1], s_side);
    cudaStreamWaitEvent(0, s_ev[1], 0);

    // GCN aggregate: S2 = norm-agg(S1) + selfloop + bias
    gcn_gather_kernel<<<gatherBlocks, 256>>>(S1, S2, gcn_b);

    // === SAGE1: side computes root term S3 = S2@Wr, main gathers S1 = agg(S2) ===
    cudaEventRecord(s_ev[2], 0);
    cudaStreamWaitEvent(s_side, s_ev[2], 0);
    gemm_one<<<gemmBlocks, 256, 0, s_side>>>(S2, s1_wr, nullptr, S3, N_NODES, 0);
    sage_gather_kernel<<<gatherBlocks, 256>>>(S2, S1);
    cudaEventRecord(s_ev[3], s_side);
    cudaStreamWaitEvent(0, s_ev[3], 0);
    gemm_one<<<gemmBlocks, 256>>>(S1, s1_wl, s1_bl, S3, N_NODES, 1);

    // === SAGE2: side computes root term S2 = S3@Wr, main gathers S1 = agg(S3) ===
    cudaEventRecord(s_ev[4], 0);
    cudaStreamWaitEvent(s_side, s_ev[4], 0);
    gemm_one<<<gemmBlocks, 256, 0, s_side>>>(S3, s2_wr, nullptr, S2, N_NODES, 0);
    sage_gather_kernel<<<gatherBlocks, 256>>>(S3, S1);
    cudaEventRecord(s_ev[5], s_side);
    cudaStreamWaitEvent(0, s_ev[5], 0);
    gemm_one<<<gemmBlocks, 256>>>(S1, s2_wl, s2_bl, S2, N_NODES, 1);

    // === pool + classifier ===
    dim3 pg(N_GRAPHS, 8);
    pool_kernel<<<pg, 128>>>(S2);
    mlp_kernel<<<N_GRAPHS, 256>>>(c_w0, c_b0, c_w1, c_b1, c_w2, c_b2, c_w3, c_b3,
                                  bn0g, bn0b, bn1g, bn1b, bn2g, bn2b, out);
}

// round 6
// speedup vs baseline: 1.1174x; 1.1174x over previous
#include <cuda_runtime.h>
#include <cuda_bf16.h>
#include <math.h>
#include <stdint.h>

// ---------------- constants ----------------
#define N_NODES  100000
#define N_EDGES  1600000
#define FEAT     128
#define N_GRAPHS 64
#define N_CLASSES 10

#define SCAN_BLK   1024
#define SCAN_NBLK  ((N_NODES + SCAN_BLK - 1) / SCAN_BLK)   // 98

// ---------------- device scratch ----------------
__device__ float g_S1[(size_t)N_NODES * FEAT];
__device__ float g_S2[(size_t)N_NODES * FEAT];
__device__ float g_S3[(size_t)N_NODES * FEAT];
__device__ __nv_bfloat16 g_B1[(size_t)N_NODES * FEAT];   // bf16 gather mirror A
__device__ __nv_bfloat16 g_B2[(size_t)N_NODES * FEAT];   // bf16 gather mirror B

__device__ int   g_src[N_EDGES];
__device__ int   g_dst[N_EDGES];
__device__ int   g_csr[N_EDGES];
__device__ int   g_batch[N_NODES];
__device__ int   g_indeg[N_NODES];
__device__ int   g_rowstart[N_NODES + 1];
__device__ int   g_pos[N_NODES];
__device__ float g_dinv[N_NODES];
__device__ float g_rcnt[N_NODES];
__device__ float g_pool[N_GRAPHS * FEAT];
__device__ int   g_gcnt[N_GRAPHS];
__device__ int   g_blocksum[SCAN_NBLK];
__device__ int   g_blockoff[SCAN_NBLK];
__device__ int   g_is64;

// ---------------- index dtype detection ----------------
__global__ void detect_kernel(const void* ei) {
    const unsigned long long* p = (const unsigned long long*)ei;
    unsigned long long v = p[threadIdx.x];
    unsigned int hi = (unsigned int)(v >> 32);
    unsigned int any = __ballot_sync(0xffffffffu, hi != 0u);
    __shared__ int s_any;
    if (threadIdx.x == 0) s_any = 0;
    __syncthreads();
    if (any != 0u && (threadIdx.x & 31) == 0) atomicOr(&s_any, 1);
    __syncthreads();
    if (threadIdx.x == 0) g_is64 = s_any ? 0 : 1;
}

__global__ void zero_kernel() {
    int i = blockIdx.x * blockDim.x + threadIdx.x;
    if (i < N_NODES) g_indeg[i] = 0;
    if (i < N_GRAPHS * FEAT) g_pool[i] = 0.0f;
}

__global__ void convert_hist_kernel(const void* ei, const void* bt) {
    int i = blockIdx.x * blockDim.x + threadIdx.x;
    const int is64 = g_is64;
    if (i < N_EDGES) {
        int s, d;
        if (is64) {
            s = (int)((const long long*)ei)[i];
            d = (int)((const long long*)ei)[(size_t)N_EDGES + i];
        } else {
            s = ((const int*)ei)[i];
            d = ((const int*)ei)[N_EDGES + i];
        }
        g_src[i] = s;
        g_dst[i] = d;
        atomicAdd(&g_indeg[d], 1);
    }
    if (i < N_NODES) {
        g_batch[i] = is64 ? (int)((const long long*)bt)[i] : ((const int*)bt)[i];
    }
}

// ---------------- 3-phase multi-block scan ----------------
__global__ __launch_bounds__(SCAN_BLK) void scan1_kernel() {
    __shared__ int warp_s[32];
    int idx = blockIdx.x * SCAN_BLK + threadIdx.x;
    int v = (idx < N_NODES) ? g_indeg[idx] : 0;
#pragma unroll
    for (int o = 16; o > 0; o >>= 1) v += __shfl_down_sync(0xffffffffu, v, o);
    int wid = threadIdx.x >> 5, lane = threadIdx.x & 31;
    if (lane == 0) warp_s[wid] = v;
    __syncthreads();
    if (wid == 0) {
        int s = (lane < SCAN_BLK / 32) ? warp_s[lane] : 0;
#pragma unroll
        for (int o = 16; o > 0; o >>= 1) s += __shfl_down_sync(0xffffffffu, s, o);
        if (lane == 0) g_blocksum[blockIdx.x] = s;
    }
}

__global__ void scan2_kernel() {
    __shared__ int sm[SCAN_NBLK];
    int t = threadIdx.x;
    int v = (t < SCAN_NBLK) ? g_blocksum[t] : 0;
    if (t < SCAN_NBLK) sm[t] = v;
    __syncthreads();
    if (t == 0) {
        int run = 0;
        for (int i = 0; i < SCAN_NBLK; i++) { int c = sm[i]; sm[i] = run; run += c; }
        g_rowstart[N_NODES] = run;
    }
    __syncthreads();
    if (t < SCAN_NBLK) g_blockoff[t] = sm[t];
}

__global__ __launch_bounds__(SCAN_BLK) void scan3_kernel() {
    __shared__ int warp_s[32];
    int idx = blockIdx.x * SCAN_BLK + threadIdx.x;
    int wid = threadIdx.x >> 5, lane = threadIdx.x & 31;
    int c = (idx < N_NODES) ? g_indeg[idx] : 0;
    int v = c;
#pragma unroll
    for (int o = 1; o < 32; o <<= 1) {
        int u = __shfl_up_sync(0xffffffffu, v, o);
        if (lane >= o) v += u;
    }
    if (lane == 31) warp_s[wid] = v;
    __syncthreads();
    if (wid == 0) {
        int s = (lane < SCAN_BLK / 32) ? warp_s[lane] : 0;
#pragma unroll
        for (int o = 1; o < 32; o <<= 1) {
            int u = __shfl_up_sync(0xffffffffu, s, o);
            if (lane >= o) s += u;
        }
        if (lane < SCAN_BLK / 32) warp_s[lane] = s;
    }
    __syncthreads();
    int excl = v - c + (wid > 0 ? warp_s[wid - 1] : 0) + g_blockoff[blockIdx.x];
    if (idx < N_NODES) {
        g_rowstart[idx] = excl;
        g_pos[idx]      = excl;
        g_dinv[idx]     = rsqrtf((float)c + 1.0f);
        g_rcnt[idx]     = 1.0f / (float)max(c, 1);
    }
}

__global__ void scatter_kernel() {
    int e = blockIdx.x * blockDim.x + threadIdx.x;
    if (e < N_EDGES) {
        int d = g_dst[e];
        int p = atomicAdd(&g_pos[d], 1);
        g_csr[p] = g_src[e];
    }
}

// ---------------- bf16 split-precision tensor-core GEMM (dual-pass fused) ----------------
// out[M,128] = A1@W1^T (+ A2@W2^T) (+bias); optional bf16 mirror write.
__device__ __forceinline__ void mma_bf16(float* c, const uint32_t* a, const uint32_t* b) {
    asm volatile(
        "mma.sync.aligned.m16n8k16.row.col.f32.bf16.bf16.f32 "
        "{%0,%1,%2,%3}, {%4,%5,%6,%7}, {%8,%9}, {%0,%1,%2,%3};\n"
        : "+f"(c[0]), "+f"(c[1]), "+f"(c[2]), "+f"(c[3])
        : "r"(a[0]), "r"(a[1]), "r"(a[2]), "r"(a[3]), "r"(b[0]), "r"(b[1]));
}

__device__ __forceinline__ void split2(float x, float y, uint32_t& hi, uint32_t& lo) {
    __nv_bfloat162 h = __floats2bfloat162_rn(x, y);
    float2 hf = __bfloat1622float2(h);
    __nv_bfloat162 l = __floats2bfloat162_rn(x - hf.x, y - hf.y);
    hi = *reinterpret_cast<uint32_t*>(&h);
    lo = *reinterpret_cast<uint32_t*>(&l);
}

#define SMW 20

__global__ __launch_bounds__(256, 2) void gemm_dual(
    const float* __restrict__ A1, const float* __restrict__ W1,
    const float* __restrict__ A2, const float* __restrict__ W2,
    const float* __restrict__ bias, float* __restrict__ out,
    __nv_bfloat16* __restrict__ outb, int M)
{
    __shared__ uint32_t sAhi[128][SMW], sAlo[128][SMW];
    __shared__ uint32_t sWhi[128][SMW], sWlo[128][SMW];

    const int t    = threadIdx.x;
    const int warp = t >> 5;
    const int lane = t & 31;
    const int wm   = warp >> 1;
    const int wn   = warp & 1;
    const int m0   = blockIdx.x * 128;
    const int r    = lane >> 2;
    const int kq   = lane & 3;

    float acc[2][8][4];
#pragma unroll
    for (int i = 0; i < 2; i++)
#pragma unroll
        for (int j = 0; j < 8; j++)
#pragma unroll
            for (int q = 0; q < 4; q++) acc[i][j][q] = 0.0f;

    const int npass = (A2 != nullptr) ? 2 : 1;
    for (int pass = 0; pass < npass; pass++) {
        const float* A = pass ? A2 : A1;
        const float* W = pass ? W2 : W1;
        for (int k0 = 0; k0 < 128; k0 += 32) {
#pragma unroll
            for (int i = 0; i < 4; i++) {
                int slot = t + i * 256;
                int row  = slot >> 3;
                int c4   = slot & 7;
                int ar   = m0 + row; if (ar >= M) ar = M - 1;
                float4 av = __ldg((const float4*)(A + (size_t)ar * 128 + k0 + c4 * 4));
                uint32_t h0, l0, h1, l1;
                split2(av.x, av.y, h0, l0);
                split2(av.z, av.w, h1, l1);
                sAhi[row][c4 * 2] = h0;  sAhi[row][c4 * 2 + 1] = h1;
                sAlo[row][c4 * 2] = l0;  sAlo[row][c4 * 2 + 1] = l1;
                float4 wv = __ldg((const float4*)(W + (size_t)row * 128 + k0 + c4 * 4));
                split2(wv.x, wv.y, h0, l0);
                split2(wv.z, wv.w, h1, l1);
                sWhi[row][c4 * 2] = h0;  sWhi[row][c4 * 2 + 1] = h1;
                sWlo[row][c4 * 2] = l0;  sWlo[row][c4 * 2 + 1] = l1;
            }
            __syncthreads();

#pragma unroll
            for (int kk = 0; kk < 32; kk += 16) {
                const int kw = kk >> 1;
                uint32_t ah[2][4], al[2][4];
#pragma unroll
                for (int mt = 0; mt < 2; mt++) {
                    int mr = wm * 32 + mt * 16;
                    ah[mt][0] = sAhi[mr + r][kw + kq];
                    ah[mt][1] = sAhi[mr + r + 8][kw + kq];
                    ah[mt][2] = sAhi[mr + r][kw + kq + 4];
                    ah[mt][3] = sAhi[mr + r + 8][kw + kq + 4];
                    al[mt][0] = sAlo[mr + r][kw + kq];
                    al[mt][1] = sAlo[mr + r + 8][kw + kq];
                    al[mt][2] = sAlo[mr + r][kw + kq + 4];
                    al[mt][3] = sAlo[mr + r + 8][kw + kq + 4];
                }
#pragma unroll
                for (int g = 0; g < 2; g++) {
                    uint32_t bh[4][2], bl[4][2];
#pragma unroll
                    for (int n2 = 0; n2 < 4; n2++) {
                        int nr = wn * 64 + g * 32 + n2 * 8 + r;
                        bh[n2][0] = sWhi[nr][kw + kq];
                        bh[n2][1] = sWhi[nr][kw + kq + 4];
                        bl[n2][0] = sWlo[nr][kw + kq];
                        bl[n2][1] = sWlo[nr][kw + kq + 4];
                    }
#pragma unroll
                    for (int mt = 0; mt < 2; mt++)
#pragma unroll
                        for (int n2 = 0; n2 < 4; n2++) {
                            float* c = acc[mt][g * 4 + n2];
                            mma_bf16(c, ah[mt], bh[n2]);
                            mma_bf16(c, ah[mt], bl[n2]);
                            mma_bf16(c, al[mt], bh[n2]);
                        }
                }
            }
            __syncthreads();
        }
    }

#pragma unroll
    for (int mt = 0; mt < 2; mt++) {
#pragma unroll
        for (int nt = 0; nt < 8; nt++) {
            int gcol = wn * 64 + nt * 8 + kq * 2;
            float b0 = 0.f, b1 = 0.f;
            if (bias) { b0 = bias[gcol]; b1 = bias[gcol + 1]; }
            int grow = m0 + wm * 32 + mt * 16 + r;
            if (grow < M) {
                float v0 = acc[mt][nt][0] + b0;
                float v1 = acc[mt][nt][1] + b1;
                float* p = out + (size_t)grow * 128 + gcol;
                p[0] = v0; p[1] = v1;
                if (outb) *(__nv_bfloat162*)(outb + (size_t)grow * 128 + gcol) =
                    __floats2bfloat162_rn(v0, v1);
            }
            int grow2 = grow + 8;
            if (grow2 < M) {
                float v0 = acc[mt][nt][2] + b0;
                float v1 = acc[mt][nt][3] + b1;
                float* p = out + (size_t)grow2 * 128 + gcol;
                p[0] = v0; p[1] = v1;
                if (outb) *(__nv_bfloat162*)(outb + (size_t)grow2 * 128 + gcol) =
                    __floats2bfloat162_rn(v0, v1);
            }
        }
    }
}

// ---------------- CSR gathers (bf16 neighbor reads, fp32 accumulate) ----------------
__global__ __launch_bounds__(256) void gcn_gather_kernel(
    const __nv_bfloat16* __restrict__ xwb, const float* __restrict__ xw,
    float* __restrict__ out, __nv_bfloat16* __restrict__ outb,
    const float* __restrict__ bias)
{
    int w = (blockIdx.x * blockDim.x + threadIdx.x) >> 5;
    int lane = threadIdx.x & 31;
    if (w >= N_NODES) return;
    int beg = g_rowstart[w], end = g_rowstart[w + 1];
    float dn = g_dinv[w];
    float4 acc = make_float4(0.f, 0.f, 0.f, 0.f);
    for (int b = beg; b < end; b += 32) {
        int nb = min(32, end - b);
        int s_l = 0; float d_l = 0.f;
        if (b + lane < end) { s_l = g_csr[b + lane]; d_l = g_dinv[s_l]; }
        for (int j = 0; j < nb; j++) {
            int   s  = __shfl_sync(0xffffffffu, s_l, j);
            float nm = __shfl_sync(0xffffffffu, d_l, j) * dn;
            uint2 raw = __ldg((const uint2*)(xwb + (size_t)s * 128) + lane);
            float2 p0 = __bfloat1622float2(*reinterpret_cast<__nv_bfloat162*>(&raw.x));
            float2 p1 = __bfloat1622float2(*reinterpret_cast<__nv_bfloat162*>(&raw.y));
            acc.x += p0.x * nm; acc.y += p0.y * nm;
            acc.z += p1.x * nm; acc.w += p1.y * nm;
        }
    }
    float4 sv = *(const float4*)(xw + (size_t)w * 128 + lane * 4);
    float d2 = dn * dn;
    float4 bv = *(const float4*)(bias + lane * 4);
    acc.x += sv.x * d2 + bv.x; acc.y += sv.y * d2 + bv.y;
    acc.z += sv.z * d2 + bv.z; acc.w += sv.w * d2 + bv.w;
    *(float4*)(out + (size_t)w * 128 + lane * 4) = acc;
    uint2 ob;
    __nv_bfloat162 q0 = __floats2bfloat162_rn(acc.x, acc.y);
    __nv_bfloat162 q1 = __floats2bfloat162_rn(acc.z, acc.w);
    ob.x = *reinterpret_cast<uint32_t*>(&q0);
    ob.y = *reinterpret_cast<uint32_t*>(&q1);
    *((uint2*)(outb + (size_t)w * 128) + lane) = ob;
}

__global__ __launch_bounds__(256) void sage_gather_kernel(
    const __nv_bfloat16* __restrict__ hb, float* __restrict__ out)
{
    int w = (blockIdx.x * blockDim.x + threadIdx.x) >> 5;
    int lane = threadIdx.x & 31;
    if (w >= N_NODES) return;
    int beg = g_rowstart[w], end = g_rowstart[w + 1];
    float4 acc = make_float4(0.f, 0.f, 0.f, 0.f);
    for (int b = beg; b < end; b += 32) {
        int nb = min(32, end - b);
        int s_l = 0;
        if (b + lane < end) s_l = g_csr[b + lane];
        for (int j = 0; j < nb; j++) {
            int s = __shfl_sync(0xffffffffu, s_l, j);
            uint2 raw = __ldg((const uint2*)(hb + (size_t)s * 128) + lane);
            float2 p0 = __bfloat1622float2(*reinterpret_cast<__nv_bfloat162*>(&raw.x));
            float2 p1 = __bfloat1622float2(*reinterpret_cast<__nv_bfloat162*>(&raw.y));
            acc.x += p0.x; acc.y += p0.y; acc.z += p1.x; acc.w += p1.y;
        }
    }
    float rc = g_rcnt[w];
    acc.x *= rc; acc.y *= rc; acc.z *= rc; acc.w *= rc;
    *(float4*)(out + (size_t)w * 128 + lane * 4) = acc;
}

// ---------------- pooling ----------------
__device__ __forceinline__ int lower_bound_batch(int val) {
    int lo = 0, hi = N_NODES;
    while (lo < hi) {
        int mid = (lo + hi) >> 1;
        if (g_batch[mid] < val) lo = mid + 1; else hi = mid;
    }
    return lo;
}

__global__ void pool_kernel(const float* __restrict__ h) {
    int g = blockIdx.x;
    int part = blockIdx.y;
    int f = threadIdx.x;
    int lo = lower_bound_batch(g);
    int hi = lower_bound_batch(g + 1);
    float acc = 0.f;
    for (int n = lo + part; n < hi; n += 8) acc += h[(size_t)n * 128 + f];
    atomicAdd(&g_pool[g * 128 + f], acc);
    if (part == 0 && f == 0) g_gcnt[g] = max(hi - lo, 1);
}

// ---------------- classifier MLP + softmax ----------------
__global__ void mlp_kernel(
    const float* __restrict__ w0, const float* __restrict__ b0,
    const float* __restrict__ w1, const float* __restrict__ b1,
    const float* __restrict__ w2, const float* __restrict__ b2,
    const float* __restrict__ w3, const float* __restrict__ b3,
    const float* __restrict__ bn0g, const float* __restrict__ bn0b,
    const float* __restrict__ bn1g, const float* __restrict__ bn1b,
    const float* __restrict__ bn2g, const float* __restrict__ bn2b,
    float* __restrict__ out)
{
    __shared__ float sin_[128], h0[200], h1[100], h2[50], lg[10];
    int g = blockIdx.x, t = threadIdx.x;
    if (t < 128) sin_[t] = g_pool[g * 128 + t] / (float)g_gcnt[g];
    __syncthreads();
    const float bnc = rsqrtf(1.0f + 1e-5f);
    if (t < 200) {
        float s = b0[t];
        const float* wr = w0 + (size_t)t * 128;
#pragma unroll 4
        for (int k = 0; k < 128; k++) s += wr[k] * sin_[k];
        h0[t] = tanhf(s * bn0g[t] * bnc + bn0b[t]);
    }
    __syncthreads();
    if (t < 100) {
        float s = b1[t];
        const float* wr = w1 + (size_t)t * 200;
#pragma unroll 4
        for (int k = 0; k < 200; k++) s += wr[k] * h0[k];
        h1[t] = tanhf(s * bn1g[t] * bnc + bn1b[t]);
    }
    __syncthreads();
    if (t < 50) {
        float s = b2[t];
        const float* wr = w2 + (size_t)t * 100;
#pragma unroll 4
        for (int k = 0; k < 100; k++) s += wr[k] * h1[k];
        h2[t] = tanhf(s * bn2g[t] * bnc + bn2b[t]);
    }
    __syncthreads();
    if (t < 10) {
        float s = b3[t];
        const float* wr = w3 + (size_t)t * 50;
#pragma unroll
        for (int k = 0; k < 50; k++) s += wr[k] * h2[k];
        lg[t] = s;
    }
    __syncthreads();
    if (t == 0) {
        float m = lg[0];
        for (int c = 1; c < N_CLASSES; c++) m = fmaxf(m, lg[c]);
        float e[N_CLASSES];
        float sum = 0.f;
        for (int c = 0; c < N_CLASSES; c++) { e[c] = expf(lg[c] - m); sum += e[c]; }
        float inv = 1.0f / sum;
        for (int c = 0; c < N_CLASSES; c++) out[g * N_CLASSES + c] = e[c] * inv;
    }
}

// ---------------- launch ----------------
extern "C" void kernel_launch(void* const* d_in, const int* in_sizes, int n_in,
                              void* d_out, int out_size)
{
    const float* x       = (const float*)d_in[0];
    const void*  ei      = d_in[1];
    const void*  bt      = d_in[2];
    const float* gcn_w   = (const float*)d_in[3];
    const float* gcn_b   = (const float*)d_in[4];
    const float* s1_wl   = (const float*)d_in[5];
    const float* s1_bl   = (const float*)d_in[6];
    const float* s1_wr   = (const float*)d_in[7];
    const float* s2_wl   = (const float*)d_in[8];
    const float* s2_bl   = (const float*)d_in[9];
    const float* s2_wr   = (const float*)d_in[10];
    const float* c_w0 = (const float*)d_in[11]; const float* c_b0 = (const float*)d_in[12];
    const float* c_w1 = (const float*)d_in[13]; const float* c_b1 = (const float*)d_in[14];
    const float* c_w2 = (const float*)d_in[15]; const float* c_b2 = (const float*)d_in[16];
    const float* c_w3 = (const float*)d_in[17]; const float* c_b3 = (const float*)d_in[18];
    const float* bn0g = (const float*)d_in[19]; const float* bn0b = (const float*)d_in[20];
    const float* bn1g = (const float*)d_in[21]; const float* bn1b = (const float*)d_in[22];
    const float* bn2g = (const float*)d_in[23]; const float* bn2b = (const float*)d_in[24];
    float* out = (float*)d_out;

    float *S1, *S2, *S3;
    __nv_bfloat16 *B1, *B2;
    cudaGetSymbolAddress((void**)&S1, g_S1);
    cudaGetSymbolAddress((void**)&S2, g_S2);
    cudaGetSymbolAddress((void**)&S3, g_S3);
    cudaGetSymbolAddress((void**)&B1, g_B1);
    cudaGetSymbolAddress((void**)&B2, g_B2);

    static cudaStream_t s_side = nullptr;
    static cudaEvent_t  s_fork = nullptr, s_join = nullptr;
    if (s_side == nullptr) {
        cudaStreamCreateWithFlags(&s_side, cudaStreamNonBlocking);
        cudaEventCreateWithFlags(&s_fork, cudaEventDisableTiming);
        cudaEventCreateWithFlags(&s_join, cudaEventDisableTiming);
    }

    const int TB = 256;
    const int nodeBlocks   = (N_NODES + TB - 1) / TB;
    const int edgeBlocks   = (N_EDGES + TB - 1) / TB;
    const int gatherBlocks = (N_NODES + 7) / 8;
    const int gemmBlocks   = (N_NODES + 127) / 128;

    // === fork: GCN GEMM overlaps CSR build (different resources: tensor vs atomics) ===
    detect_kernel<<<1, 256>>>(ei);
    cudaEventRecord(s_fork, 0);
    cudaStreamWaitEvent(s_side, s_fork, 0);
    gemm_dual<<<gemmBlocks, 256, 0, s_side>>>(x, gcn_w, nullptr, nullptr, nullptr,
                                              S1, B1, N_NODES);

    zero_kernel<<<nodeBlocks, TB>>>();
    convert_hist_kernel<<<edgeBlocks, TB>>>(ei, bt);
    scan1_kernel<<<SCAN_NBLK, SCAN_BLK>>>();
    scan2_kernel<<<1, 128>>>();
    scan3_kernel<<<SCAN_NBLK, SCAN_BLK>>>();
    scatter_kernel<<<edgeBlocks, TB>>>();

    cudaEventRecord(s_join, s_side);
    cudaStreamWaitEvent(0, s_join, 0);

    // GCN aggregate: S2 = norm-agg(bf16 S1) + selfloop(fp32) + bias; mirror -> B2
    gcn_gather_kernel<<<gatherBlocks, 256>>>(B1, S1, S2, B2, gcn_b);

    // SAGE1: S1 = mean-agg(bf16 S2); S3 = S1@Wl + bl + S2@Wr; mirror -> B1
    sage_gather_kernel<<<gatherBlocks, 256>>>(B2, S1);
    gemm_dual<<<gemmBlocks, 256>>>(S1, s1_wl, S2, s1_wr, s1_bl, S3, B1, N_NODES);

    // SAGE2: S1 = mean-agg(bf16 S3); S2 = S1@Wl + bl + S3@Wr (no mirror needed)
    sage_gather_kernel<<<gatherBlocks, 256>>>(B1, S1);
    gemm_dual<<<gemmBlocks, 256>>>(S1, s2_wl, S3, s2_wr, s2_bl, S2, nullptr, N_NODES);

    // pool + classifier
    dim3 pg(N_GRAPHS, 8);
    pool_kernel<<<pg, 128>>>(S2);
    mlp_kernel<<<N_GRAPHS, 256>>>(c_w0, c_b0, c_w1, c_b1, c_w2, c_b2, c_w3, c_b3,
                                  bn0g, bn0b, bn1g, bn1b, bn2g, bn2b, out);
}